// round 13
// baseline (speedup 1.0000x reference)
#include <cuda_runtime.h>

#define EPS 1e-8f
typedef unsigned long long ull;

constexpr int RS2 = 580;                  // img half row stride; addr = r*580 + 4*(r/6) + kh + 4*(kh>>5)
constexpr int OFF_CH0 = 20896;            // chunk buffer 0 (3232 floats)
constexpr int OFF_CH1 = 24128;            // chunk buffer 1 (3232 floats)
constexpr int OFF_ATT = OFF_CH0;          // overlay after A: [ci]*1584 + r*44 + l  (6336 <= 6464)
constexpr int OFF_W1  = 27360;
constexpr int OFF_B1v = OFF_W1 + 256;
constexpr int OFF_W2S = OFF_B1v + 8;
constexpr int OFF_B2S = OFF_W2S + 8;
constexpr int OFF_RED = OFF_B2S + 4;
constexpr int SMEM_FLOATS = OFF_RED + 160;       // 27796
constexpr int SMEM_BYTES  = SMEM_FLOATS * 4;     // 111,184 B -> 2 CTAs/SM

__device__ float g_cos[1024 * 5120];      // per-block cosine scratch

__device__ __forceinline__ ull dup2(float a) {
    ull r; asm("mov.b64 %0, {%1, %1};" : "=l"(r) : "f"(a)); return r;
}
__device__ __forceinline__ void f2(ull& d, ull a, ull b) {
    asm("fma.rn.f32x2 %0, %1, %2, %0;" : "+l"(d) : "l"(a), "l"(b));
}
__device__ __forceinline__ void up(ull v, float& lo, float& hi) {
    asm("mov.b64 {%0, %1}, %2;" : "=f"(lo), "=f"(hi) : "l"(v));
}

__global__ __launch_bounds__(192, 2)
void tg_kernel(const float* __restrict__ images, const float* __restrict__ captions,
               const int* __restrict__ cap_lens, const float* __restrict__ rare,
               const float* __restrict__ v1, const float* __restrict__ g1, const float* __restrict__ b1,
               const float* __restrict__ v2, const float* __restrict__ g2, const float* __restrict__ b2,
               const int* __restrict__ lam_p, float* __restrict__ out)
{
    extern __shared__ float sm[];
    const int tid = threadIdx.x;
    const int img = blockIdx.x;
    const int c0  = blockIdx.y * 4;
    const int bl  = blockIdx.y * 64 + blockIdx.x;

    // ---- img k-half loader: 4608 float4 / 192 thr = 24 each ----
    #define LOAD_HALF(H) { \
        const float* gsrc = images + (size_t)img * 36864 + (H) * 512; \
        _Pragma("unroll") \
        for (int s = 0; s < 24; s++) { \
            int idx = tid + 192 * s; \
            int r = idx >> 7, kf = (idx & 127) * 4; \
            *(float4*)(sm + r * RS2 + 4 * (r / 6) + kf + 4 * (kf >> 5)) = \
                *(const float4*)(gsrc + r * 1024 + kf); \
        } }

    // ---- weights preamble ----
    if (tid < 8) {
        int j = tid; float s = 0.f;
        for (int n = 0; n < 32; n++) { float v = v1[j * 32 + n]; s += v * v; }
        float inv = g1[j] / sqrtf(s);
        for (int n = 0; n < 32; n++) sm[OFF_W1 + j * 32 + n] = v1[j * 32 + n] * inv;
        sm[OFF_B1v + j] = b1[j];
    }
    if (tid == 8) {
        float w2s[8] = {0,0,0,0,0,0,0,0}; float b2s = 0.f;
        for (int k = 0; k < 6; k++) {
            float s = 0.f;
            for (int j = 0; j < 8; j++) { float v = v2[k * 8 + j]; s += v * v; }
            float inv = g2[k] / sqrtf(s);
            for (int j = 0; j < 8; j++) w2s[j] += v2[k * 8 + j] * inv;
            b2s += b2[k];
        }
        for (int j = 0; j < 8; j++) sm[OFF_W2S + j] = w2s[j];
        sm[OFF_B2S] = b2s;
    }
    const float lam = (float)(*lam_p);

    // Phase A map: lg (slow, 8 groups of 5 words) x capi (4) x rg (6, fast)
    const int lg = tid / 24, capi = (tid % 24) / 6, rg = tid % 6;
    const int lg5 = lg * 5;
    const int mylen = cap_lens[c0 + capi];
    const bool actA = (lg5 < mylen);

    ull acc[6][5];
    #pragma unroll
    for (int q = 0; q < 6; q++)
        #pragma unroll
        for (int j = 0; j < 5; j++) acc[q][j] = 0ull;

    // chunk = [4 caps][40 words][16 k]; 640 float4; 4 (guarded) per thread
    // smem chunk layout: ci*808 + l*20 + k   (808 ≡ 8 mod 32 -> conflict-free)
    #define CPA_CHUNK(KC) { \
        const int half_ = (KC) >> 5, kof_ = ((KC) & 31) * 16 + half_ * 512; \
        const int base_ = ((KC) & 1) ? OFF_CH1 : OFF_CH0; \
        _Pragma("unroll") \
        for (int s = 0; s < 4; s++) { \
            int idx = tid + 192 * s; \
            if (idx < 640) { \
                int ci_ = idx / 160, r2_ = idx % 160, l_ = r2_ >> 2, k4_ = (r2_ & 3) * 4; \
                unsigned int sa_ = (unsigned int)__cvta_generic_to_shared( \
                    sm + base_ + ci_ * 808 + l_ * 20 + k4_); \
                const float* g_ = captions + (((size_t)(c0 + ci_) * 40 + l_) << 10) + kof_ + k4_; \
                asm volatile("cp.async.cg.shared.global [%0], [%1], 16;" :: "r"(sa_), "l"(g_) : "memory"); \
            } \
        } \
        asm volatile("cp.async.commit_group;" ::: "memory"); }

    LOAD_HALF(0)
    CPA_CHUNK(0)

    // ================= Phase A: 64 chunks, depth-1 cp.async, 1 sync/chunk =================
    #pragma unroll 1
    for (int kc = 0; kc < 64; kc++) {
        asm volatile("cp.async.wait_group 0;" ::: "memory");
        __syncthreads();                       // chunk kc visible to all; prev buf free
        if (kc == 32) { LOAD_HALF(1) __syncthreads(); }
        if (kc + 1 < 64) CPA_CHUNK(kc + 1)     // into the buffer freed this iteration
        if (actA) {
            const int klocal = (kc & 31) * 16;
            const float* ib = sm + rg * 3484 + klocal + 4 * (klocal >> 5);
            const float* cb = sm + ((kc & 1) ? OFF_CH1 : OFF_CH0) + capi * 808 + lg5 * 20;
            #pragma unroll
            for (int k4 = 0; k4 < 16; k4 += 4) {
                ulonglong2 I[6], C[5];
                #pragma unroll
                for (int q = 0; q < 6; q++) I[q] = *(const ulonglong2*)(ib + q * RS2 + k4);
                #pragma unroll
                for (int j = 0; j < 5; j++) C[j] = *(const ulonglong2*)(cb + j * 20 + k4);
                #pragma unroll
                for (int q = 0; q < 6; q++)
                    #pragma unroll
                    for (int j = 0; j < 5; j++) {
                        f2(acc[q][j], I[q].x, C[j].x);
                        f2(acc[q][j], I[q].y, C[j].y);
                    }
            }
        }
    }
    __syncthreads();   // chunk region becomes ATT

    // ---- epilogue: leaky-relu + mask -> ATT (stride 44) ----
    {
        float* base = sm + OFF_ATT + capi * 1584;
        #pragma unroll
        for (int q = 0; q < 6; q++)
            #pragma unroll
            for (int j = 0; j < 5; j++) {
                float lo, hi; up(acc[q][j], lo, hi);
                float v = lo + hi;
                v = (v > 0.f ? v : 0.1f * v);
                int w = lg5 + j;
                base[(rg * 6 + q) * 44 + w] = (w < mylen) ? v : 0.f;
            }
    }
    __syncthreads();

    // ===== B1: l2 norm over words per region =====
    if (tid < 144) {
        int ci = tid / 36, r = tid % 36;
        float* row = sm + OFF_ATT + ci * 1584 + r * 44;
        float s = 0.f;
        #pragma unroll 8
        for (int l = 0; l < 40; l++) { float v = row[l]; s += v * v; }
        float inv = 1.f / (sqrtf(s) + EPS);
        #pragma unroll 8
        for (int l = 0; l < 40; l++) row[l] *= inv;
    }
    __syncthreads();

    // ===== B2: softmax over regions, in-place (column l private) =====
    if (tid < 160) {
        int ci = tid / 40, l = tid % 40;
        int len = cap_lens[c0 + ci];
        float* base = sm + OFF_ATT + ci * 1584;
        if (l < len) {
            float e[36]; float ssum = 0.f;
            #pragma unroll
            for (int r = 0; r < 36; r++) { e[r] = __expf(base[r * 44 + l] * lam); ssum += e[r]; }
            float inv = 1.f / ssum;
            #pragma unroll
            for (int r = 0; r < 36; r++) base[r * 44 + l] = e[r] * inv;
        } else {
            #pragma unroll
            for (int r = 0; r < 36; r++) base[r * 44 + l] = 0.f;
        }
    }
    __syncthreads();

    // ===== Phase C: per-warp (ci, 4-word group); lane = nbl; img via GLOBAL/L1 =====
    {
        const int warp = tid >> 5, nbl = tid & 31;
        const float* imgg = images + (size_t)img * 36864 + nbl * 32;
        #pragma unroll 1
        for (int g = warp; g < 40; g += 6) {
            const int ci = g & 3, wg = g >> 2;
            const int w0 = wg * 4;
            const int len = cap_lens[c0 + ci];
            if (w0 >= len) continue;
            const float* a2 = sm + OFF_ATT + ci * 1584 + w0;
            const float* capg = captions + (((size_t)(c0 + ci) * 40 + w0) << 10);
            float W12[4] = {0,0,0,0}, CN[4] = {0,0,0,0}, QN[4] = {0,0,0,0};
            #pragma unroll
            for (int h = 0; h < 2; h++) {
                ull wc[4][8];
                #pragma unroll
                for (int w = 0; w < 4; w++)
                    #pragma unroll
                    for (int e = 0; e < 8; e++) wc[w][e] = 0ull;
                const float* ih = imgg + h * 16;
                #pragma unroll 4
                for (int r = 0; r < 36; r++) {
                    float4 av = *(const float4*)(a2 + r * 44);
                    const ulonglong2* ip = (const ulonglong2*)(ih + r * 1024);
                    ulonglong2 v0 = ip[0], v1 = ip[1], v2 = ip[2], v3 = ip[3];
                    #define CW(W, AV) { ull d_ = dup2(AV); \
                        f2(wc[W][0], d_, v0.x); f2(wc[W][1], d_, v0.y); \
                        f2(wc[W][2], d_, v1.x); f2(wc[W][3], d_, v1.y); \
                        f2(wc[W][4], d_, v2.x); f2(wc[W][5], d_, v2.y); \
                        f2(wc[W][6], d_, v3.x); f2(wc[W][7], d_, v3.y); }
                    CW(0, av.x) CW(1, av.y) CW(2, av.z) CW(3, av.w)
                    #undef CW
                }
                #pragma unroll
                for (int w = 0; w < 4; w++) {
                    const float* qp = capg + w * 1024 + nbl * 32 + h * 16;
                    float4 qa = *(const float4*)qp;
                    float4 qb = *(const float4*)(qp + 4);
                    float4 qc = *(const float4*)(qp + 8);
                    float4 qd = *(const float4*)(qp + 12);
                    float lo, hi;
                    up(wc[w][0], lo, hi); W12[w] += lo * qa.x + hi * qa.y; CN[w] += lo * lo + hi * hi; QN[w] += qa.x * qa.x + qa.y * qa.y;
                    up(wc[w][1], lo, hi); W12[w] += lo * qa.z + hi * qa.w; CN[w] += lo * lo + hi * hi; QN[w] += qa.z * qa.z + qa.w * qa.w;
                    up(wc[w][2], lo, hi); W12[w] += lo * qb.x + hi * qb.y; CN[w] += lo * lo + hi * hi; QN[w] += qb.x * qb.x + qb.y * qb.y;
                    up(wc[w][3], lo, hi); W12[w] += lo * qb.z + hi * qb.w; CN[w] += lo * lo + hi * hi; QN[w] += qb.z * qb.z + qb.w * qb.w;
                    up(wc[w][4], lo, hi); W12[w] += lo * qc.x + hi * qc.y; CN[w] += lo * lo + hi * hi; QN[w] += qc.x * qc.x + qc.y * qc.y;
                    up(wc[w][5], lo, hi); W12[w] += lo * qc.z + hi * qc.w; CN[w] += lo * lo + hi * hi; QN[w] += qc.z * qc.z + qc.w * qc.w;
                    up(wc[w][6], lo, hi); W12[w] += lo * qd.x + hi * qd.y; CN[w] += lo * lo + hi * hi; QN[w] += qd.x * qd.x + qd.y * qd.y;
                    up(wc[w][7], lo, hi); W12[w] += lo * qd.z + hi * qd.w; CN[w] += lo * lo + hi * hi; QN[w] += qd.z * qd.z + qd.w * qd.w;
                }
            }
            #pragma unroll
            for (int w = 0; w < 4; w++)
                g_cos[(size_t)bl * 5120 + ci * 1280 + (w0 + w) * 32 + nbl] =
                    W12[w] / fmaxf(sqrtf(CN[w]) * sqrtf(QN[w]), EPS);
        }
    }
    __syncthreads();

    // ===== Phase D: weight-normed MLP + masked mean =====
    if (tid < 160) {
        int ci = tid / 40, l = tid % 40;
        int len = cap_lens[c0 + ci];
        float res = 0.f;
        if (l < len) {
            const float* rr = rare + ((size_t)(c0 + ci) * 40 + l) * 32;
            const float* cb = g_cos + (size_t)bl * 5120 + ci * 1280 + l * 32;
            float x[32];
            #pragma unroll
            for (int n = 0; n < 32; n++) x[n] = cb[n] + 0.4f * rr[n];
            float persum = sm[OFF_B2S];
            #pragma unroll
            for (int j = 0; j < 8; j++) {
                float hsum = sm[OFF_B1v + j];
                const float* wr = sm + OFF_W1 + j * 32;
                #pragma unroll
                for (int n = 0; n < 32; n++) hsum = fmaf(x[n], wr[n], hsum);
                persum = fmaf(tanhf(hsum), sm[OFF_W2S + j], persum);
            }
            res = persum;
        }
        sm[OFF_RED + tid] = res;
    }
    __syncthreads();
    if (tid < 4) {
        int len = cap_lens[c0 + tid];
        float s = 0.f;
        for (int l = 0; l < len; l++) s += sm[OFF_RED + tid * 40 + l];
        out[(size_t)img * 64 + (c0 + tid)] = s / (float)(len * 6);
    }
}

extern "C" void kernel_launch(void* const* d_in, const int* in_sizes, int n_in,
                              void* d_out, int out_size) {
    const float* images   = (const float*)d_in[0];
    const float* captions = (const float*)d_in[1];
    const int*   cap_lens = (const int*)d_in[2];
    const float* rare     = (const float*)d_in[3];
    const float* v1       = (const float*)d_in[4];
    const float* g1       = (const float*)d_in[5];
    const float* b1       = (const float*)d_in[6];
    const float* v2       = (const float*)d_in[7];
    const float* g2       = (const float*)d_in[8];
    const float* b2       = (const float*)d_in[9];
    const int*   lam      = (const int*)d_in[12];
    float* out = (float*)d_out;

    cudaFuncSetAttribute(tg_kernel, cudaFuncAttributeMaxDynamicSharedMemorySize, SMEM_BYTES);
    tg_kernel<<<dim3(64, 16, 1), 192, SMEM_BYTES>>>(
        images, captions, cap_lens, rare, v1, g1, b1, v2, g2, b2, lam, out);
}

// round 14
// speedup vs baseline: 1.8724x; 1.8724x over previous
#include <cuda_runtime.h>

#define EPS 1e-8f
typedef unsigned long long ull;

constexpr int RS = 1184;                 // img row stride (floats), ≡0 mod 32
// img addr: r*RS + 4*(r/6) + k + 4*(k/32)
constexpr int CAP_ROW = 36;              // cap chunk row (floats): 32 + 4
constexpr int CAP_CAP = 1448;            // per-cap chunk stride

constexpr int OFF_CAP = 42656;           // after img region
constexpr int OFF_ATT = 48448;           // OFF_CAP + 4*1448; ATT stride 1476; COS overlays ci*1320+l*33+nbl
constexpr int OFF_W1  = 54352;           // OFF_ATT + 4*1476
constexpr int OFF_B1  = OFF_W1 + 256;
constexpr int OFF_W2S = OFF_B1 + 8;
constexpr int OFF_B2S = OFF_W2S + 8;
constexpr int OFF_RED = OFF_B2S + 4;
constexpr int SMEM_FLOATS = OFF_RED + 160;
constexpr int SMEM_BYTES  = SMEM_FLOATS * 4;   // ~219 KB

__device__ __forceinline__ ull dup2(float a) {
    ull r; asm("mov.b64 %0, {%1, %1};" : "=l"(r) : "f"(a)); return r;
}
__device__ __forceinline__ void f2(ull& d, ull a, ull b) {
    asm("fma.rn.f32x2 %0, %1, %2, %0;" : "+l"(d) : "l"(a), "l"(b));
}
__device__ __forceinline__ void up(ull v, float& lo, float& hi) {
    asm("mov.b64 {%0, %1}, %2;" : "=f"(lo), "=f"(hi) : "l"(v));
}

__global__ __launch_bounds__(480, 1)
void tg_kernel(const float* __restrict__ images, const float* __restrict__ captions,
               const int* __restrict__ cap_lens, const float* __restrict__ rare,
               const float* __restrict__ v1, const float* __restrict__ g1, const float* __restrict__ b1,
               const float* __restrict__ v2, const float* __restrict__ g2, const float* __restrict__ b2,
               const int* __restrict__ lam_p, float* __restrict__ out)
{
    extern __shared__ float sm[];
    const int tid = threadIdx.x;
    const int img = blockIdx.x;
    const int c0  = blockIdx.y * 4;

    // ---- preamble: image -> SMEM, RS=1184 + per-6-row-block skew + per-32-k skew ----
    {
        const float4* g4 = (const float4*)(images + (size_t)img * 36 * 1024);
        for (int i = tid; i < 9216; i += 480) {
            int r = i >> 8, kf = (i & 255) * 4;
            *(float4*)(sm + r * RS + 4 * (r / 6) + kf + 4 * (kf >> 5)) = g4[i];
        }
    }
    if (tid < 8) {
        int j = tid; float s = 0.f;
        for (int n = 0; n < 32; n++) { float v = v1[j * 32 + n]; s += v * v; }
        float inv = g1[j] / sqrtf(s);
        for (int n = 0; n < 32; n++) sm[OFF_W1 + j * 32 + n] = v1[j * 32 + n] * inv;
        sm[OFF_B1 + j] = b1[j];
    }
    if (tid == 8) {
        float w2s[8] = {0,0,0,0,0,0,0,0}; float b2s = 0.f;
        for (int k = 0; k < 6; k++) {
            float s = 0.f;
            for (int j = 0; j < 8; j++) { float v = v2[k * 8 + j]; s += v * v; }
            float inv = g2[k] / sqrtf(s);
            for (int j = 0; j < 8; j++) w2s[j] += v2[k * 8 + j] * inv;
            b2s += b2[k];
        }
        for (int j = 0; j < 8; j++) sm[OFF_W2S + j] = w2s[j];
        sm[OFF_B2S] = b2s;
    }
    const float lam = (float)(*lam_p);

    // Phase A map: khalf = tid/240; t2: wg (40 groups of 4 words across 4 caps), rg fast
    const int khalf = tid / 240, t2 = tid % 240;
    const int wg = t2 / 6, rg = t2 % 6;
    const int capi = wg / 10, wlocal = (wg % 10) * 4;
    const int mylen = cap_lens[c0 + capi];
    const bool actA = (wlocal < mylen);

    ull acc[6][4];
    #pragma unroll
    for (int q = 0; q < 6; q++)
        #pragma unroll
        for (int j = 0; j < 4; j++) acc[q][j] = 0ull;

    // caption chunk prefetch (1280 float4 / 480 thr -> 3 regs, third guarded)
    float4 pf0, pf1, pf2;
    const int i0 = tid, i1 = tid + 480, i2 = tid + 960;

    #define PF_LOAD(REG, I, KC) if ((I) < 1280) { \
        int ci_ = (I) / 320, r2_ = (I) % 320, l_ = r2_ >> 3, k4_ = r2_ & 7; \
        REG = *(const float4*)(captions + (((size_t)(c0 + ci_) * 40 + l_) << 10) + (KC) * 32 + k4_ * 4); }
    #define PF_STORE(REG, I) if ((I) < 1280) { \
        int ci_ = (I) / 320, r2_ = (I) % 320, l_ = r2_ >> 3, k4_ = r2_ & 7; \
        *(float4*)(sm + OFF_CAP + ci_ * CAP_CAP + l_ * CAP_ROW + k4_ * 4) = REG; }

    PF_LOAD(pf0, i0, 0) PF_LOAD(pf1, i1, 0) PF_LOAD(pf2, i2, 0)

    const float* ibase = sm + rg * (6 * RS) + 4 * rg + khalf * 16;
    const float* cbase = sm + OFF_CAP + capi * CAP_CAP + wlocal * CAP_ROW + khalf * 16;

    __syncthreads();

    // ================= Phase A: S = img . cap^T (k-packed FFMA2) =================
    for (int kc = 0; kc < 32; kc++) {
        __syncthreads();
        PF_STORE(pf0, i0) PF_STORE(pf1, i1) PF_STORE(pf2, i2)
        __syncthreads();
        if (kc + 1 < 32) {
            PF_LOAD(pf0, i0, kc + 1) PF_LOAD(pf1, i1, kc + 1) PF_LOAD(pf2, i2, kc + 1)
        }
        if (actA) {
            const float* ib = ibase + kc * 36;
            #pragma unroll
            for (int k4 = 0; k4 < 16; k4 += 4) {
                ulonglong2 I[6], C[4];
                #pragma unroll
                for (int q = 0; q < 6; q++) I[q] = *(const ulonglong2*)(ib + q * RS + k4);
                #pragma unroll
                for (int j = 0; j < 4; j++) C[j] = *(const ulonglong2*)(cbase + j * CAP_ROW + k4);
                #pragma unroll
                for (int q = 0; q < 6; q++)
                    #pragma unroll
                    for (int j = 0; j < 4; j++) {
                        f2(acc[q][j], I[q].x, C[j].x);
                        f2(acc[q][j], I[q].y, C[j].y);
                    }
            }
        }
    }
    __syncthreads();

    // ---- epilogue: khalf reduction through ATT, leaky-relu + mask ----
    {
        float* base = sm + OFF_ATT + capi * 1476;
        if (khalf) {
            #pragma unroll
            for (int q = 0; q < 6; q++)
                #pragma unroll
                for (int j = 0; j < 4; j++) {
                    float lo, hi; up(acc[q][j], lo, hi);
                    base[(rg * 6 + q) * 41 + wlocal + j] = lo + hi;
                }
        }
        __syncthreads();
        if (!khalf) {
            #pragma unroll
            for (int q = 0; q < 6; q++)
                #pragma unroll
                for (int j = 0; j < 4; j++) {
                    float lo, hi; up(acc[q][j], lo, hi);
                    int w = wlocal + j;
                    float v = lo + hi + base[(rg * 6 + q) * 41 + w];
                    v = (v > 0.f ? v : 0.1f * v);
                    base[(rg * 6 + q) * 41 + w] = (w < mylen) ? v : 0.f;
                }
        }
    }
    __syncthreads();

    // ===== B1: l2 norm over words per region =====
    if (tid < 144) {
        int ci = tid / 36, r = tid % 36;
        float* row = sm + OFF_ATT + ci * 1476 + r * 41;
        float s = 0.f;
        #pragma unroll 8
        for (int l = 0; l < 40; l++) { float v = row[l]; s += v * v; }
        float inv = 1.f / (sqrtf(s) + EPS);
        #pragma unroll 8
        for (int l = 0; l < 40; l++) row[l] *= inv;
    }
    __syncthreads();

    // ===== B2: softmax over regions -> A2[ci][r*40+l] at OFF_CAP (stride 1440) =====
    if (tid < 160) {
        int ci = tid / 40, l = tid % 40;
        int len = cap_lens[c0 + ci];
        float* A2 = sm + OFF_CAP + ci * 1440;
        if (l < len) {
            const float* Sb = sm + OFF_ATT + ci * 1476;
            float e[36]; float ssum = 0.f;
            #pragma unroll
            for (int r = 0; r < 36; r++) { e[r] = __expf(Sb[r * 41 + l] * lam); ssum += e[r]; }
            float inv = 1.f / ssum;
            #pragma unroll
            for (int r = 0; r < 36; r++) A2[r * 40 + l] = e[r] * inv;
        } else {
            #pragma unroll
            for (int r = 0; r < 36; r++) A2[r * 40 + l] = 0.f;
        }
    }
    __syncthreads();

    // ===== Phase C: per-warp (ci, 4-word group), lane = nbl; whole-warp skip =====
    {
        const int warp = tid >> 5, nbl = tid & 31;
        #pragma unroll 1
        for (int g = warp; g < 40; g += 15) {
            const int ci = g / 10, wgC = g % 10;
            const int w0 = wgC * 4;
            const int len = cap_lens[c0 + ci];
            if (w0 >= len) continue;
            const float* A2 = sm + OFF_CAP + ci * 1440 + w0;
            const float* capg = captions + (((size_t)(c0 + ci) * 40 + w0) << 10);
            float W12[4] = {0,0,0,0}, CN[4] = {0,0,0,0}, QN[4] = {0,0,0,0};
            #pragma unroll
            for (int h = 0; h < 2; h++) {
                ull wc[4][8];
                #pragma unroll
                for (int wd = 0; wd < 4; wd++)
                    #pragma unroll
                    for (int e = 0; e < 8; e++) wc[wd][e] = 0ull;
                #pragma unroll 1
                for (int rb = 0; rb < 6; rb++) {
                    const float* imgb = sm + rb * (6 * RS) + 4 * rb + nbl * 36 + h * 16;
                    const float* a2b = A2 + rb * 240;
                    #pragma unroll
                    for (int q = 0; q < 6; q++) {
                        float4 av = *(const float4*)(a2b + q * 40);
                        ull d0 = dup2(av.x), d1 = dup2(av.y), d2 = dup2(av.z), d3 = dup2(av.w);
                        const ulonglong2* ip = (const ulonglong2*)(imgb + q * RS);
                        ulonglong2 q0 = ip[0], q1 = ip[1], q2 = ip[2], q3 = ip[3];
                        f2(wc[0][0], d0, q0.x); f2(wc[0][1], d0, q0.y);
                        f2(wc[0][2], d0, q1.x); f2(wc[0][3], d0, q1.y);
                        f2(wc[0][4], d0, q2.x); f2(wc[0][5], d0, q2.y);
                        f2(wc[0][6], d0, q3.x); f2(wc[0][7], d0, q3.y);
                        f2(wc[1][0], d1, q0.x); f2(wc[1][1], d1, q0.y);
                        f2(wc[1][2], d1, q1.x); f2(wc[1][3], d1, q1.y);
                        f2(wc[1][4], d1, q2.x); f2(wc[1][5], d1, q2.y);
                        f2(wc[1][6], d1, q3.x); f2(wc[1][7], d1, q3.y);
                        f2(wc[2][0], d2, q0.x); f2(wc[2][1], d2, q0.y);
                        f2(wc[2][2], d2, q1.x); f2(wc[2][3], d2, q1.y);
                        f2(wc[2][4], d2, q2.x); f2(wc[2][5], d2, q2.y);
                        f2(wc[2][6], d2, q3.x); f2(wc[2][7], d2, q3.y);
                        f2(wc[3][0], d3, q0.x); f2(wc[3][1], d3, q0.y);
                        f2(wc[3][2], d3, q1.x); f2(wc[3][3], d3, q1.y);
                        f2(wc[3][4], d3, q2.x); f2(wc[3][5], d3, q2.y);
                        f2(wc[3][6], d3, q3.x); f2(wc[3][7], d3, q3.y);
                    }
                }
                #pragma unroll
                for (int wd = 0; wd < 4; wd++) {
                    const float4* q4 = (const float4*)(capg + wd * 1024 + nbl * 32 + h * 16);
                    float4 qa = q4[0], qb = q4[1], qc = q4[2], qd = q4[3];
                    float lo, hi;
                    up(wc[wd][0], lo, hi); W12[wd] += lo * qa.x + hi * qa.y; CN[wd] += lo * lo + hi * hi; QN[wd] += qa.x * qa.x + qa.y * qa.y;
                    up(wc[wd][1], lo, hi); W12[wd] += lo * qa.z + hi * qa.w; CN[wd] += lo * lo + hi * hi; QN[wd] += qa.z * qa.z + qa.w * qa.w;
                    up(wc[wd][2], lo, hi); W12[wd] += lo * qb.x + hi * qb.y; CN[wd] += lo * lo + hi * hi; QN[wd] += qb.x * qb.x + qb.y * qb.y;
                    up(wc[wd][3], lo, hi); W12[wd] += lo * qb.z + hi * qb.w; CN[wd] += lo * lo + hi * hi; QN[wd] += qb.z * qb.z + qb.w * qb.w;
                    up(wc[wd][4], lo, hi); W12[wd] += lo * qc.x + hi * qc.y; CN[wd] += lo * lo + hi * hi; QN[wd] += qc.x * qc.x + qc.y * qc.y;
                    up(wc[wd][5], lo, hi); W12[wd] += lo * qc.z + hi * qc.w; CN[wd] += lo * lo + hi * hi; QN[wd] += qc.z * qc.z + qc.w * qc.w;
                    up(wc[wd][6], lo, hi); W12[wd] += lo * qd.x + hi * qd.y; CN[wd] += lo * lo + hi * hi; QN[wd] += qd.x * qd.x + qd.y * qd.y;
                    up(wc[wd][7], lo, hi); W12[wd] += lo * qd.z + hi * qd.w; CN[wd] += lo * lo + hi * hi; QN[wd] += qd.z * qd.z + qd.w * qd.w;
                }
            }
            #pragma unroll
            for (int wd = 0; wd < 4; wd++)
                sm[OFF_ATT + ci * 1320 + (w0 + wd) * 33 + nbl] =
                    W12[wd] / fmaxf(sqrtf(CN[wd]) * sqrtf(QN[wd]), EPS);
        }
    }
    __syncthreads();

    // ===== Phase D: weight-normed MLP + masked mean =====
    if (tid < 160) {
        int ci = tid / 40, l = tid % 40;
        int len = cap_lens[c0 + ci];
        float res = 0.f;
        if (l < len) {
            const float* rr = rare + ((size_t)(c0 + ci) * 40 + l) * 32;
            const float* cb = sm + OFF_ATT + ci * 1320 + l * 33;
            float x[32];
            #pragma unroll
            for (int n = 0; n < 32; n++) x[n] = cb[n] + 0.4f * rr[n];
            float persum = sm[OFF_B2S];
            #pragma unroll
            for (int j = 0; j < 8; j++) {
                float hsum = sm[OFF_B1 + j];
                const float* wr = sm + OFF_W1 + j * 32;
                #pragma unroll
                for (int n = 0; n < 32; n++) hsum = fmaf(x[n], wr[n], hsum);
                persum = fmaf(tanhf(hsum), sm[OFF_W2S + j], persum);
            }
            res = persum;
        }
        sm[OFF_RED + tid] = res;
    }
    __syncthreads();
    if (tid < 4) {
        int len = cap_lens[c0 + tid];
        float s = 0.f;
        for (int l = 0; l < len; l++) s += sm[OFF_RED + tid * 40 + l];
        out[(size_t)img * 64 + (c0 + tid)] = s / (float)(len * 6);
    }
}

extern "C" void kernel_launch(void* const* d_in, const int* in_sizes, int n_in,
                              void* d_out, int out_size) {
    const float* images   = (const float*)d_in[0];
    const float* captions = (const float*)d_in[1];
    const int*   cap_lens = (const int*)d_in[2];
    const float* rare     = (const float*)d_in[3];
    const float* v1       = (const float*)d_in[4];
    const float* g1       = (const float*)d_in[5];
    const float* b1       = (const float*)d_in[6];
    const float* v2       = (const float*)d_in[7];
    const float* g2       = (const float*)d_in[8];
    const float* b2       = (const float*)d_in[9];
    const int*   lam      = (const int*)d_in[12];
    float* out = (float*)d_out;

    cudaFuncSetAttribute(tg_kernel, cudaFuncAttributeMaxDynamicSharedMemorySize, SMEM_BYTES);
    tg_kernel<<<dim3(64, 16, 1), 480, SMEM_BYTES>>>(
        images, captions, cap_lens, rare, v1, g1, b1, v2, g2, b2, lam, out);
}

// round 15
// speedup vs baseline: 2.0877x; 1.1150x over previous
#include <cuda_runtime.h>

#define EPS 1e-8f
typedef unsigned long long ull;

constexpr int RS = 1184;                 // img row stride (floats), ≡0 mod 32
// img addr: r*RS + 4*(r/6) + k + 4*(k/32)

constexpr int OFF_ATT = 42656;           // ATT/A2 in-place region: ci*1584 + r*44 + l
constexpr int OFF_W1  = 48992;
constexpr int OFF_B1v = OFF_W1 + 256;
constexpr int OFF_W2S = OFF_B1v + 8;
constexpr int OFF_B2S = OFF_W2S + 8;
constexpr int OFF_RED = OFF_B2S + 4;
constexpr int SMEM_FLOATS = OFF_RED + 172;      // 49440
constexpr int SMEM_BYTES  = SMEM_FLOATS * 4;    // 197,760 B -> ~30 KB L1D left

__device__ float g_cos[1024 * 5120];     // per-block cosine scratch (L2-resident)

__device__ __forceinline__ ull dup2(float a) {
    ull r; asm("mov.b64 %0, {%1, %1};" : "=l"(r) : "f"(a)); return r;
}
__device__ __forceinline__ void f2(ull& d, ull a, ull b) {
    asm("fma.rn.f32x2 %0, %1, %2, %0;" : "+l"(d) : "l"(a), "l"(b));
}
__device__ __forceinline__ void up(ull v, float& lo, float& hi) {
    asm("mov.b64 {%0, %1}, %2;" : "=f"(lo), "=f"(hi) : "l"(v));
}

__global__ __launch_bounds__(384, 1)
void tg_kernel(const float* __restrict__ images, const float* __restrict__ captions,
               const int* __restrict__ cap_lens, const float* __restrict__ rare,
               const float* __restrict__ v1, const float* __restrict__ g1, const float* __restrict__ b1,
               const float* __restrict__ v2, const float* __restrict__ g2, const float* __restrict__ b2,
               const int* __restrict__ lam_p, float* __restrict__ out)
{
    extern __shared__ float sm[];
    const int tid = threadIdx.x;
    const int img = blockIdx.x;
    const int c0  = blockIdx.y * 4;
    const int bl  = blockIdx.y * 64 + blockIdx.x;

    // ---- preamble: image -> SMEM, RS=1184 + per-6-row-block skew + per-32-k skew ----
    {
        const float4* g4 = (const float4*)(images + (size_t)img * 36 * 1024);
        for (int i = tid; i < 9216; i += 384) {
            int r = i >> 8, kf = (i & 255) * 4;
            *(float4*)(sm + r * RS + 4 * (r / 6) + kf + 4 * (kf >> 5)) = g4[i];
        }
    }
    if (tid < 8) {
        int j = tid; float s = 0.f;
        for (int n = 0; n < 32; n++) { float v = v1[j * 32 + n]; s += v * v; }
        float inv = g1[j] / sqrtf(s);
        for (int n = 0; n < 32; n++) sm[OFF_W1 + j * 32 + n] = v1[j * 32 + n] * inv;
        sm[OFF_B1v + j] = b1[j];
    }
    if (tid == 8) {
        float w2s[8] = {0,0,0,0,0,0,0,0}; float b2s = 0.f;
        for (int k = 0; k < 6; k++) {
            float s = 0.f;
            for (int j = 0; j < 8; j++) { float v = v2[k * 8 + j]; s += v * v; }
            float inv = g2[k] / sqrtf(s);
            for (int j = 0; j < 8; j++) w2s[j] += v2[k * 8 + j] * inv;
            b2s += b2[k];
        }
        for (int j = 0; j < 8; j++) sm[OFF_W2S + j] = w2s[j];
        sm[OFF_B2S] = b2s;
    }
    const float lam = (float)(*lam_p);

    // Phase A map: khalf x [lg (slow) x capi x rg (fast)]
    const int khalf = tid / 192, t2 = tid % 192;
    const int lg = t2 / 24, r3 = t2 % 24, capi = r3 / 6, rg = r3 % 6;
    const int lg5 = lg * 5;
    const int mylen = cap_lens[c0 + capi];
    const bool actA = (lg5 < mylen);

    ull acc[6][5];
    #pragma unroll
    for (int q = 0; q < 6; q++)
        #pragma unroll
        for (int j = 0; j < 5; j++) acc[q][j] = 0ull;

    const float* ibase = sm + rg * (6 * RS) + 4 * rg + khalf * 16;
    const float* capgA = captions + (size_t)(c0 + capi) * 40960 + lg5 * 1024 + khalf * 16;

    __syncthreads();   // img resident

    // ========== Phase A: S = img . cap^T — captions direct from L2/L1, NO barriers ==========
    if (actA) {
        #pragma unroll 2
        for (int kc = 0; kc < 32; kc++) {
            const float* ib = ibase + kc * 36;
            const float* cg = capgA + kc * 32;
            #pragma unroll
            for (int k4 = 0; k4 < 16; k4 += 4) {
                ulonglong2 I[6], C[5];
                #pragma unroll
                for (int q = 0; q < 6; q++) I[q] = *(const ulonglong2*)(ib + q * RS + k4);
                #pragma unroll
                for (int j = 0; j < 5; j++) C[j] = *(const ulonglong2*)(cg + j * 1024 + k4);
                #pragma unroll
                for (int q = 0; q < 6; q++)
                    #pragma unroll
                    for (int j = 0; j < 5; j++) {
                        f2(acc[q][j], I[q].x, C[j].x);
                        f2(acc[q][j], I[q].y, C[j].y);
                    }
            }
        }
    }

    // ---- epilogue: khalf reduction through ATT (stride 44), leaky-relu + mask ----
    {
        float* base = sm + OFF_ATT + capi * 1584;
        if (khalf) {
            #pragma unroll
            for (int q = 0; q < 6; q++)
                #pragma unroll
                for (int j = 0; j < 5; j++) {
                    float lo, hi; up(acc[q][j], lo, hi);
                    base[(rg * 6 + q) * 44 + lg5 + j] = lo + hi;
                }
        }
        __syncthreads();
        if (!khalf) {
            #pragma unroll
            for (int q = 0; q < 6; q++)
                #pragma unroll
                for (int j = 0; j < 5; j++) {
                    float lo, hi; up(acc[q][j], lo, hi);
                    int w = lg5 + j;
                    float v = lo + hi + base[(rg * 6 + q) * 44 + w];
                    v = (v > 0.f ? v : 0.1f * v);
                    base[(rg * 6 + q) * 44 + w] = (w < mylen) ? v : 0.f;
                }
        }
    }
    __syncthreads();

    // ===== B1: l2 norm over words per region =====
    if (tid < 144) {
        int ci = tid / 36, r = tid % 36;
        float* row = sm + OFF_ATT + ci * 1584 + r * 44;
        float s = 0.f;
        #pragma unroll 8
        for (int l = 0; l < 40; l++) { float v = row[l]; s += v * v; }
        float inv = 1.f / (sqrtf(s) + EPS);
        #pragma unroll 8
        for (int l = 0; l < 40; l++) row[l] *= inv;
    }
    __syncthreads();

    // ===== B2: softmax over regions, IN-PLACE (column l private per thread) =====
    if (tid < 160) {
        int ci = tid / 40, l = tid % 40;
        int len = cap_lens[c0 + ci];
        float* base = sm + OFF_ATT + ci * 1584;
        if (l < len) {
            float e[36]; float ssum = 0.f;
            #pragma unroll
            for (int r = 0; r < 36; r++) { e[r] = __expf(base[r * 44 + l] * lam); ssum += e[r]; }
            float inv = 1.f / ssum;
            #pragma unroll
            for (int r = 0; r < 36; r++) base[r * 44 + l] = e[r] * inv;
        } else {
            #pragma unroll
            for (int r = 0; r < 36; r++) base[r * 44 + l] = 0.f;
        }
    }
    __syncthreads();

    // ===== Phase C: per-warp (ci, 4-word group), lane = nbl; whole-warp skip =====
    {
        const int warp = tid >> 5, nbl = tid & 31;
        #pragma unroll 1
        for (int g = warp; g < 40; g += 12) {
            const int ci = g / 10, wgC = g % 10;
            const int w0 = wgC * 4;
            const int len = cap_lens[c0 + ci];
            if (w0 >= len) continue;
            const float* A2 = sm + OFF_ATT + ci * 1584 + w0;
            const float* capg = captions + (((size_t)(c0 + ci) * 40 + w0) << 10);
            float W12[4] = {0,0,0,0}, CN[4] = {0,0,0,0}, QN[4] = {0,0,0,0};
            #pragma unroll
            for (int h = 0; h < 2; h++) {
                ull wc[4][8];
                #pragma unroll
                for (int wd = 0; wd < 4; wd++)
                    #pragma unroll
                    for (int e = 0; e < 8; e++) wc[wd][e] = 0ull;
                #pragma unroll 1
                for (int rb = 0; rb < 6; rb++) {
                    const float* imgb = sm + rb * (6 * RS) + 4 * rb + nbl * 36 + h * 16;
                    const float* a2b = A2 + rb * (6 * 44);
                    #pragma unroll
                    for (int q = 0; q < 6; q++) {
                        float4 av = *(const float4*)(a2b + q * 44);
                        ull d0 = dup2(av.x), d1 = dup2(av.y), d2 = dup2(av.z), d3 = dup2(av.w);
                        const ulonglong2* ip = (const ulonglong2*)(imgb + q * RS);
                        ulonglong2 q0 = ip[0], q1 = ip[1], q2 = ip[2], q3 = ip[3];
                        f2(wc[0][0], d0, q0.x); f2(wc[0][1], d0, q0.y);
                        f2(wc[0][2], d0, q1.x); f2(wc[0][3], d0, q1.y);
                        f2(wc[0][4], d0, q2.x); f2(wc[0][5], d0, q2.y);
                        f2(wc[0][6], d0, q3.x); f2(wc[0][7], d0, q3.y);
                        f2(wc[1][0], d1, q0.x); f2(wc[1][1], d1, q0.y);
                        f2(wc[1][2], d1, q1.x); f2(wc[1][3], d1, q1.y);
                        f2(wc[1][4], d1, q2.x); f2(wc[1][5], d1, q2.y);
                        f2(wc[1][6], d1, q3.x); f2(wc[1][7], d1, q3.y);
                        f2(wc[2][0], d2, q0.x); f2(wc[2][1], d2, q0.y);
                        f2(wc[2][2], d2, q1.x); f2(wc[2][3], d2, q1.y);
                        f2(wc[2][4], d2, q2.x); f2(wc[2][5], d2, q2.y);
                        f2(wc[2][6], d2, q3.x); f2(wc[2][7], d2, q3.y);
                        f2(wc[3][0], d3, q0.x); f2(wc[3][1], d3, q0.y);
                        f2(wc[3][2], d3, q1.x); f2(wc[3][3], d3, q1.y);
                        f2(wc[3][4], d3, q2.x); f2(wc[3][5], d3, q2.y);
                        f2(wc[3][6], d3, q3.x); f2(wc[3][7], d3, q3.y);
                    }
                }
                #pragma unroll
                for (int wd = 0; wd < 4; wd++) {
                    const float4* q4 = (const float4*)(capg + wd * 1024 + nbl * 32 + h * 16);
                    float4 qa = q4[0], qb = q4[1], qc = q4[2], qd = q4[3];
                    float lo, hi;
                    up(wc[wd][0], lo, hi); W12[wd] += lo * qa.x + hi * qa.y; CN[wd] += lo * lo + hi * hi; QN[wd] += qa.x * qa.x + qa.y * qa.y;
                    up(wc[wd][1], lo, hi); W12[wd] += lo * qa.z + hi * qa.w; CN[wd] += lo * lo + hi * hi; QN[wd] += qa.z * qa.z + qa.w * qa.w;
                    up(wc[wd][2], lo, hi); W12[wd] += lo * qb.x + hi * qb.y; CN[wd] += lo * lo + hi * hi; QN[wd] += qb.x * qb.x + qb.y * qb.y;
                    up(wc[wd][3], lo, hi); W12[wd] += lo * qb.z + hi * qb.w; CN[wd] += lo * lo + hi * hi; QN[wd] += qb.z * qb.z + qb.w * qb.w;
                    up(wc[wd][4], lo, hi); W12[wd] += lo * qc.x + hi * qc.y; CN[wd] += lo * lo + hi * hi; QN[wd] += qc.x * qc.x + qc.y * qc.y;
                    up(wc[wd][5], lo, hi); W12[wd] += lo * qc.z + hi * qc.w; CN[wd] += lo * lo + hi * hi; QN[wd] += qc.z * qc.z + qc.w * qc.w;
                    up(wc[wd][6], lo, hi); W12[wd] += lo * qd.x + hi * qd.y; CN[wd] += lo * lo + hi * hi; QN[wd] += qd.x * qd.x + qd.y * qd.y;
                    up(wc[wd][7], lo, hi); W12[wd] += lo * qd.z + hi * qd.w; CN[wd] += lo * lo + hi * hi; QN[wd] += qd.z * qd.z + qd.w * qd.w;
                }
            }
            #pragma unroll
            for (int wd = 0; wd < 4; wd++)
                g_cos[(size_t)bl * 5120 + ci * 1280 + (w0 + wd) * 32 + nbl] =
                    W12[wd] / fmaxf(sqrtf(CN[wd]) * sqrtf(QN[wd]), EPS);
        }
    }
    __syncthreads();

    // ===== Phase D: weight-normed MLP + masked mean (cos from global scratch) =====
    if (tid < 160) {
        int ci = tid / 40, l = tid % 40;
        int len = cap_lens[c0 + ci];
        float res = 0.f;
        if (l < len) {
            const float* rr = rare + ((size_t)(c0 + ci) * 40 + l) * 32;
            const float* cb = g_cos + (size_t)bl * 5120 + ci * 1280 + l * 32;
            float x[32];
            #pragma unroll
            for (int n = 0; n < 32; n++) x[n] = cb[n] + 0.4f * rr[n];
            float persum = sm[OFF_B2S];
            #pragma unroll
            for (int j = 0; j < 8; j++) {
                float hsum = sm[OFF_B1v + j];
                const float* wr = sm + OFF_W1 + j * 32;
                #pragma unroll
                for (int n = 0; n < 32; n++) hsum = fmaf(x[n], wr[n], hsum);
                persum = fmaf(tanhf(hsum), sm[OFF_W2S + j], persum);
            }
            res = persum;
        }
        sm[OFF_RED + tid] = res;
    }
    __syncthreads();
    if (tid < 4) {
        int len = cap_lens[c0 + tid];
        float s = 0.f;
        for (int l = 0; l < len; l++) s += sm[OFF_RED + tid * 40 + l];
        out[(size_t)img * 64 + (c0 + tid)] = s / (float)(len * 6);
    }
}

extern "C" void kernel_launch(void* const* d_in, const int* in_sizes, int n_in,
                              void* d_out, int out_size) {
    const float* images   = (const float*)d_in[0];
    const float* captions = (const float*)d_in[1];
    const int*   cap_lens = (const int*)d_in[2];
    const float* rare     = (const float*)d_in[3];
    const float* v1       = (const float*)d_in[4];
    const float* g1       = (const float*)d_in[5];
    const float* b1       = (const float*)d_in[6];
    const float* v2       = (const float*)d_in[7];
    const float* g2       = (const float*)d_in[8];
    const float* b2       = (const float*)d_in[9];
    const int*   lam      = (const int*)d_in[12];
    float* out = (float*)d_out;

    cudaFuncSetAttribute(tg_kernel, cudaFuncAttributeMaxDynamicSharedMemorySize, SMEM_BYTES);
    tg_kernel<<<dim3(64, 16, 1), 384, SMEM_BYTES>>>(
        images, captions, cap_lens, rare, v1, g1, b1, v2, g2, b2, lam, out);
}